// round 15
// baseline (speedup 1.0000x reference)
#include <cuda_runtime.h>
#include <cuda_fp16.h>
#include <math.h>
#include <stdint.h>

#define S_IMG 2048
#define S_TXT 256
#define SEQ   2304
#define DIM   3072
#define HEADS 24
#define HD    128

#define QSCALE 0.12751743f   // (1/sqrt(128)) * log2(e)

// ---------------- scratch (device globals: allocation-free) ----------------
__device__ __half g_xh[SEQ * DIM];
__device__ __half g_qh[SEQ * DIM];
__device__ __half g_kh[SEQ * DIM];
__device__ __half g_vh[SEQ * DIM];
__device__ __half g_ah[S_IMG * DIM];
__device__ __half g_wqh[DIM * DIM];
__device__ __half g_wkh[DIM * DIM];
__device__ __half g_wvh[DIM * DIM];
__device__ __half g_woh[DIM * DIM];

__device__ __forceinline__ float ex2(float x) {
    float r; asm("ex2.approx.f32 %0, %1;" : "=f"(r) : "f"(x)); return r;
}
__device__ __forceinline__ void cpasync16(uint32_t s, const void* g) {
    asm volatile("cp.async.cg.shared.global [%0], [%1], 16;" :: "r"(s), "l"(g));
}
__device__ __forceinline__ void mma_f16(float* c, const uint32_t* a, const uint32_t* b) {
    asm volatile("mma.sync.aligned.m16n8k16.row.col.f32.f16.f16.f32 "
        "{%0,%1,%2,%3},{%4,%5,%6,%7},{%8,%9},{%0,%1,%2,%3};"
        : "+f"(c[0]), "+f"(c[1]), "+f"(c[2]), "+f"(c[3])
        : "r"(a[0]), "r"(a[1]), "r"(a[2]), "r"(a[3]), "r"(b[0]), "r"(b[1]));
}
__device__ __forceinline__ void ldsm4(uint32_t* r, uint32_t addr) {
    asm volatile("ldmatrix.sync.aligned.m8n8.x4.shared.b16 {%0,%1,%2,%3}, [%4];"
        : "=r"(r[0]), "=r"(r[1]), "=r"(r[2]), "=r"(r[3]) : "r"(addr));
}
__device__ __forceinline__ void ldsm4t(uint32_t* r, uint32_t addr) {
    asm volatile("ldmatrix.sync.aligned.m8n8.x4.trans.shared.b16 {%0,%1,%2,%3}, [%4];"
        : "=r"(r[0]), "=r"(r[1]), "=r"(r[2]), "=r"(r[3]) : "r"(addr));
}
__device__ __forceinline__ uint32_t packh2(float x, float y) {
    __half2 h = __floats2half2_rn(x, y);
    return *reinterpret_cast<uint32_t*>(&h);
}

// ---------------- concat hidden || encoder -> fp16 (8 floats/thread) ----------------
__global__ void concat_xh(const float* __restrict__ hid, const float* __restrict__ enc) {
    int i = blockIdx.x * 256 + threadIdx.x;
    const int n_img = S_IMG * DIM / 8;
    const float4* src = (i < n_img) ? reinterpret_cast<const float4*>(hid) + 2 * i
                                    : reinterpret_cast<const float4*>(enc) + 2 * (i - n_img);
    float4 a = src[0], b = src[1];
    uint4 o;
    o.x = packh2(a.x, a.y); o.y = packh2(a.z, a.w);
    o.z = packh2(b.x, b.y); o.w = packh2(b.z, b.w);
    reinterpret_cast<uint4*>(g_xh)[i] = o;
}

// ---------------- all 4 W fp32 -> fp16, one launch ----------------
__global__ void conv_w4(const float* __restrict__ Wq, const float* __restrict__ Wk,
                        const float* __restrict__ Wv, const float* __restrict__ Wo) {
    const float* src;
    __half* dst;
    switch (blockIdx.y) {
        case 0: src = Wq; dst = g_wqh; break;
        case 1: src = Wk; dst = g_wkh; break;
        case 2: src = Wv; dst = g_wvh; break;
        default: src = Wo; dst = g_woh; break;
    }
    int i = blockIdx.x * 256 + threadIdx.x;
    float4 a = reinterpret_cast<const float4*>(src)[2 * i];
    float4 b = reinterpret_cast<const float4*>(src)[2 * i + 1];
    uint4 o;
    o.x = packh2(a.x, a.y); o.y = packh2(a.z, a.w);
    o.z = packh2(b.x, b.y); o.w = packh2(b.z, b.w);
    reinterpret_cast<uint4*>(dst)[i] = o;
}

// ---------------- shared GEMM mainloop (128x128 tile, BK=64, 3 stages) ----------------
#define GA_PITCH 72                       // halves per A row (64 + 8 pad)
#define GB_PITCH 136                      // halves per B row (128 + 8 pad)
#define GA_BYTES (128 * GA_PITCH * 2)     // 18432
#define GB_BYTES (64 * GB_PITCH * 2)      // 17408
#define GSTAGE   (GA_BYTES + GB_BYTES)    // 35840
#define GEMM_SMEM (3 * GSTAGE)            // 107520

struct GemmCtx {
    int t, lane, warp, wm, wn, grp, kq, row0, col0;
    uint32_t sbase;
};

__device__ __forceinline__ void gemm_mainloop(
    GemmCtx& g, const __half* __restrict__ A, const __half* __restrict__ B,
    float c[4][8][4])
{
    #pragma unroll
    for (int mi = 0; mi < 4; mi++)
        #pragma unroll
        for (int ni = 0; ni < 8; ni++)
            #pragma unroll
            for (int r = 0; r < 4; r++) c[mi][ni][r] = 0.0f;

    const int KT = DIM / 64;   // 48
    auto load_stage = [&](int st, int k0) {
        uint32_t sa = g.sbase + st * GSTAGE;
        uint32_t sb = sa + GA_BYTES;
        #pragma unroll
        for (int i = 0; i < 8; i++) {
            int idx = g.t + i * 128;
            int ar = idx >> 3, ac = idx & 7;
            cpasync16(sa + (ar * GA_PITCH + ac * 8) * 2,
                      A + (size_t)(g.row0 + ar) * DIM + k0 + ac * 8);
            int br = idx >> 4, bc = idx & 15;
            cpasync16(sb + (br * GB_PITCH + bc * 8) * 2,
                      B + (size_t)(k0 + br) * DIM + g.col0 + bc * 8);
        }
    };

    load_stage(0, 0);
    asm volatile("cp.async.commit_group;");
    load_stage(1, 64);
    asm volatile("cp.async.commit_group;");

    const uint32_t aoff = ((g.lane & 15) * GA_PITCH + (g.lane >> 4) * 8) * 2;
    const uint32_t boff = ((g.lane & 15) * GB_PITCH + (g.lane >> 4) * 8) * 2;

    for (int kt = 0; kt < KT; kt++) {
        asm volatile("cp.async.wait_group 1;");
        __syncthreads();

        if (kt + 2 < KT) load_stage((kt + 2) % 3, (kt + 2) * 64);
        asm volatile("cp.async.commit_group;");

        const uint32_t sa = g.sbase + (kt % 3) * GSTAGE;
        const uint32_t sb = sa + GA_BYTES;

        #pragma unroll
        for (int ks = 0; ks < 4; ks++) {
            uint32_t ah[4][4], bh[8][2];
            #pragma unroll
            for (int mi = 0; mi < 4; mi++)
                ldsm4(ah[mi], sa + aoff + ((g.wm + mi * 16) * GA_PITCH + ks * 16) * 2);
            #pragma unroll
            for (int np = 0; np < 4; np++) {
                uint32_t rh[4];
                ldsm4t(rh, sb + boff + (ks * 16 * GB_PITCH + g.wn + np * 16) * 2);
                bh[2 * np][0] = rh[0]; bh[2 * np][1] = rh[1];
                bh[2 * np + 1][0] = rh[2]; bh[2 * np + 1][1] = rh[3];
            }
            #pragma unroll
            for (int mi = 0; mi < 4; mi++)
                #pragma unroll
                for (int ni = 0; ni < 8; ni++)
                    mma_f16(c[mi][ni], ah[mi], bh[ni]);
        }
    }
    __syncthreads();
}

// ---------------- fused QKV GEMM: gridDim.z = 3 selects Q/K/V ----------------
__global__ __launch_bounds__(128, 2) void gemm_qkv(
    const float* __restrict__ bq, const float* __restrict__ bk, const float* __restrict__ bv,
    const float* __restrict__ nqw, const float* __restrict__ nkw,
    const float* __restrict__ rc, const float* __restrict__ rs)
{
    extern __shared__ char smraw[];
    GemmCtx g;
    g.t = threadIdx.x; g.lane = g.t & 31; g.warp = g.t >> 5;
    g.wm = (g.warp & 1) * 64; g.wn = (g.warp >> 1) * 64;
    g.grp = g.lane >> 2; g.kq = g.lane & 3;
    g.row0 = blockIdx.y * 128; g.col0 = blockIdx.x * 128;
    g.sbase = (uint32_t)__cvta_generic_to_shared(smraw);

    const int z = blockIdx.z;
    const __half* B = (z == 0) ? g_wqh : (z == 1) ? g_wkh : g_wvh;
    const float* bias = (z == 0) ? bq : (z == 1) ? bk : bv;

    float c[4][8][4];
    gemm_mainloop(g, g_xh, B, c);

    const bool img = (g.row0 < S_IMG);
    const int wm = g.wm, wn = g.wn, grp = g.grp, kq = g.kq;
    const int row0 = g.row0, col0 = g.col0;

    if (z <= 1) {
        __half* oh = (z == 0) ? g_qh : g_kh;
        const float* nw = (z == 0) ? nqw : nkw;
        const float fold = (z == 0) ? QSCALE : 1.0f;

        float* srow = reinterpret_cast<float*>(smraw);     // [2][128] partial row sums
        const int wnh = wn >> 6;
        float ss0[4], ss1[4];
        #pragma unroll
        for (int mi = 0; mi < 4; mi++) {
            ss0[mi] = 0.0f; ss1[mi] = 0.0f;
            #pragma unroll
            for (int ni = 0; ni < 8; ni++) {
                const int cg = col0 + wn + ni * 8 + 2 * kq;
                float2 bb = *reinterpret_cast<const float2*>(&bias[cg]);
                c[mi][ni][0] += bb.x; c[mi][ni][1] += bb.y;
                c[mi][ni][2] += bb.x; c[mi][ni][3] += bb.y;
                ss0[mi] += c[mi][ni][0] * c[mi][ni][0] + c[mi][ni][1] * c[mi][ni][1];
                ss1[mi] += c[mi][ni][2] * c[mi][ni][2] + c[mi][ni][3] * c[mi][ni][3];
            }
            ss0[mi] += __shfl_xor_sync(0xffffffffu, ss0[mi], 1);
            ss0[mi] += __shfl_xor_sync(0xffffffffu, ss0[mi], 2);
            ss1[mi] += __shfl_xor_sync(0xffffffffu, ss1[mi], 1);
            ss1[mi] += __shfl_xor_sync(0xffffffffu, ss1[mi], 2);
        }
        if (kq == 0) {
            #pragma unroll
            for (int mi = 0; mi < 4; mi++) {
                srow[wnh * 128 + wm + mi * 16 + grp]     = ss0[mi];
                srow[wnh * 128 + wm + mi * 16 + grp + 8] = ss1[mi];
            }
        }
        __syncthreads();
        #pragma unroll
        for (int mi = 0; mi < 4; mi++) {
            const int rl0 = wm + mi * 16 + grp, rl1 = rl0 + 8;
            const int r0 = row0 + rl0, r1 = row0 + rl1;
            const float rr0 = rsqrtf((srow[rl0] + srow[128 + rl0]) * (1.0f / HD) + 1e-6f);
            const float rr1 = rsqrtf((srow[rl1] + srow[128 + rl1]) * (1.0f / HD) + 1e-6f);
            #pragma unroll
            for (int ni = 0; ni < 8; ni++) {
                const int d = wn + ni * 8 + 2 * kq;
                const int cg = col0 + d;
                float2 w2 = *reinterpret_cast<const float2*>(&nw[d]);
                float v0 = c[mi][ni][0] * rr0 * w2.x;
                float v1 = c[mi][ni][1] * rr0 * w2.y;
                float v2 = c[mi][ni][2] * rr1 * w2.x;
                float v3 = c[mi][ni][3] * rr1 * w2.y;
                if (img) {
                    float2 c20 = *reinterpret_cast<const float2*>(&rc[(size_t)r0 * HD + d]);
                    float2 s20 = *reinterpret_cast<const float2*>(&rs[(size_t)r0 * HD + d]);
                    float2 c21 = *reinterpret_cast<const float2*>(&rc[(size_t)r1 * HD + d]);
                    float2 s21 = *reinterpret_cast<const float2*>(&rs[(size_t)r1 * HD + d]);
                    float e0 = v0, o0 = v1, e1 = v2, o1 = v3;
                    v0 = e0 * c20.x - o0 * s20.x;
                    v1 = o0 * c20.y + e0 * s20.y;
                    v2 = e1 * c21.x - o1 * s21.x;
                    v3 = o1 * c21.y + e1 * s21.y;
                }
                v0 *= fold; v1 *= fold; v2 *= fold; v3 *= fold;
                *reinterpret_cast<__half2*>(&oh[(size_t)r0 * DIM + cg]) =
                    __floats2half2_rn(v0, v1);
                *reinterpret_cast<__half2*>(&oh[(size_t)r1 * DIM + cg]) =
                    __floats2half2_rn(v2, v3);
            }
        }
    } else {
        #pragma unroll
        for (int mi = 0; mi < 4; mi++) {
            const int r0 = row0 + wm + mi * 16 + grp, r1 = r0 + 8;
            #pragma unroll
            for (int ni = 0; ni < 8; ni++) {
                const int cg = col0 + wn + ni * 8 + 2 * kq;
                float2 bb = *reinterpret_cast<const float2*>(&bias[cg]);
                *reinterpret_cast<__half2*>(&g_vh[(size_t)r0 * DIM + cg]) =
                    __floats2half2_rn(c[mi][ni][0] + bb.x, c[mi][ni][1] + bb.y);
                *reinterpret_cast<__half2*>(&g_vh[(size_t)r1 * DIM + cg]) =
                    __floats2half2_rn(c[mi][ni][2] + bb.x, c[mi][ni][3] + bb.y);
            }
        }
    }
}

// ---------------- output GEMM: attn(img) @ Wo + bo -> d_out ----------------
__global__ __launch_bounds__(128, 2) void gemm_out(
    const float* __restrict__ bias, float* __restrict__ outF)
{
    extern __shared__ char smraw[];
    GemmCtx g;
    g.t = threadIdx.x; g.lane = g.t & 31; g.warp = g.t >> 5;
    g.wm = (g.warp & 1) * 64; g.wn = (g.warp >> 1) * 64;
    g.grp = g.lane >> 2; g.kq = g.lane & 3;
    g.row0 = blockIdx.y * 128; g.col0 = blockIdx.x * 128;
    g.sbase = (uint32_t)__cvta_generic_to_shared(smraw);

    float c[4][8][4];
    gemm_mainloop(g, g_ah, g_woh, c);

    #pragma unroll
    for (int mi = 0; mi < 4; mi++) {
        const int r0 = g.row0 + g.wm + mi * 16 + g.grp, r1 = r0 + 8;
        #pragma unroll
        for (int ni = 0; ni < 8; ni++) {
            const int cg = g.col0 + g.wn + ni * 8 + 2 * g.kq;
            float2 bb = *reinterpret_cast<const float2*>(&bias[cg]);
            *reinterpret_cast<float2*>(&outF[(size_t)r0 * DIM + cg]) =
                make_float2(c[mi][ni][0] + bb.x, c[mi][ni][1] + bb.y);
            *reinterpret_cast<float2*>(&outF[(size_t)r1 * DIM + cg]) =
                make_float2(c[mi][ni][2] + bb.x, c[mi][ni][3] + bb.y);
        }
    }
}

// ---------------- flash attention: 64-row Q, 128 thr, 3 CTA/SM ----------------
// smem (bytes): Q 17408 | K 2 stages x 17408 | V 1 stage 17408 = 69632
#define AO_Q  0
#define AO_K  17408
#define AO_V  52224
#define ATTN_SMEM 69632

__global__ __launch_bounds__(128, 3) void attn_tc(float* __restrict__ out) {
    extern __shared__ __half sh[];
    const int t = threadIdx.x, lane = t & 31, w = t >> 5;
    const int grp = lane >> 2, kq = lane & 3;
    const int h = blockIdx.y, q0 = blockIdx.x * 64, m0 = w * 16;
    const uint32_t sb = (uint32_t)__cvta_generic_to_shared(sh);

    auto load_q = [&]() {
        #pragma unroll
        for (int i = 0; i < 8; i++) {
            int idx = t + i * 128;                   // 64 rows x 16 chunks
            int r = idx >> 4, cch = idx & 15;
            cpasync16(sb + AO_Q + r * 272 + cch * 16,
                      g_qh + (size_t)(q0 + r) * DIM + h * HD + cch * 8);
        }
    };
    auto load_k = [&](int st, int k0) {
        uint32_t kb = sb + AO_K + st * 17408;
        #pragma unroll
        for (int i = 0; i < 8; i++) {
            int idx = t + i * 128;
            int r = idx >> 4, cch = idx & 15;
            cpasync16(kb + r * 272 + cch * 16,
                      g_kh + (size_t)(k0 + r) * DIM + h * HD + cch * 8);
        }
    };
    auto load_v = [&](int k0) {
        uint32_t vb = sb + AO_V;
        #pragma unroll
        for (int i = 0; i < 8; i++) {
            int idx = t + i * 128;
            int r = idx >> 4, cch = idx & 15;
            cpasync16(vb + r * 272 + cch * 16,
                      g_vh + (size_t)(k0 + r) * DIM + h * HD + cch * 8);
        }
    };

    load_q();
    asm volatile("cp.async.commit_group;");      // G: Q
    load_k(0, 0);
    load_v(0);
    asm volatile("cp.async.commit_group;");      // G: K0+V0
    load_k(1, 64);
    asm volatile("cp.async.commit_group;");      // G: K1

    float O[16][4];
    #pragma unroll
    for (int nt = 0; nt < 16; nt++)
        #pragma unroll
        for (int r = 0; r < 4; r++) O[nt][r] = 0.0f;
    float mrow0 = -INFINITY, mrow1 = -INFINITY, lrow0 = 0.0f, lrow1 = 0.0f;

    const uint32_t qoff = ((m0 + (lane & 15)) * 272 + (lane >> 4) * 16);
    const uint32_t koff = ((lane & 15) * 272 + (lane >> 4) * 16);

    for (int kt = 0; kt < 36; kt++) {
        asm volatile("cp.async.wait_group 1;");   // K(kt)+V(kt) resident; K(kt+1) may fly
        __syncthreads();

        const int st = kt & 1;
        const uint32_t kbh = sb + AO_K + st * 17408;
        const uint32_t vbb = sb + AO_V;

        // --- S = Q K^T (single fp16, Q frags reloaded per iter) ---
        float S[8][4];
        #pragma unroll
        for (int n = 0; n < 8; n++)
            #pragma unroll
            for (int r = 0; r < 4; r++) S[n][r] = 0.0f;

        #pragma unroll
        for (int ks = 0; ks < 8; ks++) {
            uint32_t qa[4];
            ldsm4(qa, sb + AO_Q + qoff + ks * 32);
            #pragma unroll
            for (int nb = 0; nb < 4; nb++) {
                uint32_t kh4[4];
                ldsm4(kh4, kbh + koff + nb * 16 * 272 + ks * 32);
                uint32_t bh0[2] = {kh4[0], kh4[2]}, bh1[2] = {kh4[1], kh4[3]};
                mma_f16(S[2 * nb], qa, bh0);
                mma_f16(S[2 * nb + 1], qa, bh1);
            }
        }

        // --- online softmax (log2 domain) ---
        float mx0 = -INFINITY, mx1 = -INFINITY;
        #pragma unroll
        for (int n = 0; n < 8; n++) {
            mx0 = fmaxf(mx0, fmaxf(S[n][0], S[n][1]));
            mx1 = fmaxf(mx1, fmaxf(S[n][2], S[n][3]));
        }
        mx0 = fmaxf(mx0, __shfl_xor_sync(0xffffffffu, mx0, 1));
        mx0 = fmaxf(mx0, __shfl_xor_sync(0xffffffffu, mx0, 2));
        mx1 = fmaxf(mx1, __shfl_xor_sync(0xffffffffu, mx1, 1));
        mx1 = fmaxf(mx1, __shfl_xor_sync(0xffffffffu, mx1, 2));

        float mn0 = fmaxf(mrow0, mx0), mn1 = fmaxf(mrow1, mx1);
        float a0 = ex2(mrow0 - mn0), a1 = ex2(mrow1 - mn1);
        float rs0 = 0.0f, rs1 = 0.0f;
        #pragma unroll
        for (int n = 0; n < 8; n++) {
            S[n][0] = ex2(S[n][0] - mn0);
            S[n][1] = ex2(S[n][1] - mn0);
            S[n][2] = ex2(S[n][2] - mn1);
            S[n][3] = ex2(S[n][3] - mn1);
            rs0 += S[n][0] + S[n][1];
            rs1 += S[n][2] + S[n][3];
        }
        rs0 += __shfl_xor_sync(0xffffffffu, rs0, 1);
        rs0 += __shfl_xor_sync(0xffffffffu, rs0, 2);
        rs1 += __shfl_xor_sync(0xffffffffu, rs1, 1);
        rs1 += __shfl_xor_sync(0xffffffffu, rs1, 2);
        lrow0 = lrow0 * a0 + rs0;
        lrow1 = lrow1 * a1 + rs1;
        mrow0 = mn0; mrow1 = mn1;

        #pragma unroll
        for (int nt = 0; nt < 16; nt++) {
            O[nt][0] *= a0; O[nt][1] *= a0;
            O[nt][2] *= a1; O[nt][3] *= a1;
        }

        // --- repack P -> A fragments ---
        uint32_t pa[4][4];
        #pragma unroll
        for (int ks2 = 0; ks2 < 4; ks2++) {
            pa[ks2][0] = packh2(S[2 * ks2][0],     S[2 * ks2][1]);
            pa[ks2][1] = packh2(S[2 * ks2][2],     S[2 * ks2][3]);
            pa[ks2][2] = packh2(S[2 * ks2 + 1][0], S[2 * ks2 + 1][1]);
            pa[ks2][3] = packh2(S[2 * ks2 + 1][2], S[2 * ks2 + 1][3]);
        }

        // --- O += P V (V via trans ldmatrix) ---
        #pragma unroll
        for (int ks2 = 0; ks2 < 4; ks2++) {
            #pragma unroll
            for (int db = 0; db < 8; db++) {
                uint32_t v4[4];
                ldsm4t(v4, vbb + koff + (ks2 * 16) * 272 + db * 32);
                uint32_t b0[2] = {v4[0], v4[1]}, b1[2] = {v4[2], v4[3]};
                mma_f16(O[2 * db], pa[ks2], b0);
                mma_f16(O[2 * db + 1], pa[ks2], b1);
            }
        }

        // V(kt) and K-stage st consumed; refill (separate groups keep wait math exact)
        __syncthreads();
        if (kt + 1 < 36) {
            load_v((kt + 1) * 64);
            asm volatile("cp.async.commit_group;");   // G: V(kt+1)
        }
        if (kt + 2 < 36) {
            load_k(st, (kt + 2) * 64);
            asm volatile("cp.async.commit_group;");   // G: K(kt+2)
        }
    }

    // ---- epilogue ----
    const float inv0 = 1.0f / lrow0, inv1 = 1.0f / lrow1;
    const int r = q0 + m0 + grp;
    if (blockIdx.x < 32) {
        #pragma unroll
        for (int nt = 0; nt < 16; nt++) {
            int cc = h * HD + nt * 8 + 2 * kq;
            *reinterpret_cast<__half2*>(&g_ah[(size_t)r * DIM + cc]) =
                __floats2half2_rn(O[nt][0] * inv0, O[nt][1] * inv0);
            *reinterpret_cast<__half2*>(&g_ah[(size_t)(r + 8) * DIM + cc]) =
                __floats2half2_rn(O[nt][2] * inv1, O[nt][3] * inv1);
        }
    } else {
        #pragma unroll
        for (int nt = 0; nt < 16; nt++) {
            int cc = h * HD + nt * 8 + 2 * kq;
            *reinterpret_cast<float2*>(&out[(size_t)r * DIM + cc]) =
                make_float2(O[nt][0] * inv0, O[nt][1] * inv0);
            *reinterpret_cast<float2*>(&out[(size_t)(r + 8) * DIM + cc]) =
                make_float2(O[nt][2] * inv1, O[nt][3] * inv1);
        }
    }
}

// ---------------- launch ----------------
extern "C" void kernel_launch(void* const* d_in, const int* in_sizes, int n_in,
                              void* d_out, int out_size) {
    const float* hid  = (const float*)d_in[0];
    const float* enc  = (const float*)d_in[1];
    const float* rcos = (const float*)d_in[2];
    const float* rsin = (const float*)d_in[3];
    const float* Wq   = (const float*)d_in[4];
    const float* bq   = (const float*)d_in[5];
    const float* Wk   = (const float*)d_in[6];
    const float* bk   = (const float*)d_in[7];
    const float* Wv   = (const float*)d_in[8];
    const float* bv   = (const float*)d_in[9];
    const float* nqw  = (const float*)d_in[10];
    const float* nkw  = (const float*)d_in[11];
    const float* Wo   = (const float*)d_in[12];
    const float* bo   = (const float*)d_in[13];
    float* out = (float*)d_out;

    cudaFuncSetAttribute(gemm_qkv, cudaFuncAttributeMaxDynamicSharedMemorySize, GEMM_SMEM);
    cudaFuncSetAttribute(gemm_out, cudaFuncAttributeMaxDynamicSharedMemorySize, GEMM_SMEM);
    cudaFuncSetAttribute(attn_tc, cudaFuncAttributeMaxDynamicSharedMemorySize, ATTN_SMEM);

    concat_xh<<<SEQ * DIM / 2048, 256>>>(hid, enc);

    dim3 gw(DIM * DIM / 2048, 4);
    conv_w4<<<gw, 256>>>(Wq, Wk, Wv, Wo);

    dim3 gqkv(DIM / 128, SEQ / 128, 3);
    gemm_qkv<<<gqkv, 128, GEMM_SMEM>>>(bq, bk, bv, nqw, nkw, rcos, rsin);

    dim3 ga(SEQ / 64, HEADS);
    attn_tc<<<ga, 128, ATTN_SMEM>>>(out);

    dim3 gout(DIM / 128, S_IMG / 128);
    gemm_out<<<gout, 128, GEMM_SMEM>>>(bo, out);
}

// round 16
// speedup vs baseline: 1.0417x; 1.0417x over previous
#include <cuda_runtime.h>
#include <cuda_fp16.h>
#include <math.h>
#include <stdint.h>

#define S_IMG 2048
#define S_TXT 256
#define SEQ   2304
#define DIM   3072
#define HEADS 24
#define HD    128

#define QSCALE 0.12751743f   // (1/sqrt(128)) * log2(e)
#define SMAX   16.5f         // fixed softmax shift: |logit*log2e| <= 128*QSCALE = 16.32

// ---------------- scratch (device globals: allocation-free) ----------------
__device__ __half g_xh[SEQ * DIM];
__device__ __half g_qh[SEQ * DIM];
__device__ __half g_kh[SEQ * DIM];
__device__ __half g_vh[SEQ * DIM];
__device__ __half g_ah[S_IMG * DIM];
__device__ __half g_wqh[DIM * DIM];
__device__ __half g_wkh[DIM * DIM];
__device__ __half g_wvh[DIM * DIM];
__device__ __half g_woh[DIM * DIM];

__device__ __forceinline__ float ex2(float x) {
    float r; asm("ex2.approx.f32 %0, %1;" : "=f"(r) : "f"(x)); return r;
}
__device__ __forceinline__ void cpasync16(uint32_t s, const void* g) {
    asm volatile("cp.async.cg.shared.global [%0], [%1], 16;" :: "r"(s), "l"(g));
}
__device__ __forceinline__ void mma_f16(float* c, const uint32_t* a, const uint32_t* b) {
    asm volatile("mma.sync.aligned.m16n8k16.row.col.f32.f16.f16.f32 "
        "{%0,%1,%2,%3},{%4,%5,%6,%7},{%8,%9},{%0,%1,%2,%3};"
        : "+f"(c[0]), "+f"(c[1]), "+f"(c[2]), "+f"(c[3])
        : "r"(a[0]), "r"(a[1]), "r"(a[2]), "r"(a[3]), "r"(b[0]), "r"(b[1]));
}
__device__ __forceinline__ void ldsm4(uint32_t* r, uint32_t addr) {
    asm volatile("ldmatrix.sync.aligned.m8n8.x4.shared.b16 {%0,%1,%2,%3}, [%4];"
        : "=r"(r[0]), "=r"(r[1]), "=r"(r[2]), "=r"(r[3]) : "r"(addr));
}
__device__ __forceinline__ void ldsm4t(uint32_t* r, uint32_t addr) {
    asm volatile("ldmatrix.sync.aligned.m8n8.x4.trans.shared.b16 {%0,%1,%2,%3}, [%4];"
        : "=r"(r[0]), "=r"(r[1]), "=r"(r[2]), "=r"(r[3]) : "r"(addr));
}
__device__ __forceinline__ uint32_t packh2(float x, float y) {
    __half2 h = __floats2half2_rn(x, y);
    return *reinterpret_cast<uint32_t*>(&h);
}

// ---------------- concat hidden || encoder -> fp16 (8 floats/thread) ----------------
__global__ void concat_xh(const float* __restrict__ hid, const float* __restrict__ enc) {
    int i = blockIdx.x * 256 + threadIdx.x;
    const int n_img = S_IMG * DIM / 8;
    const float4* src = (i < n_img) ? reinterpret_cast<const float4*>(hid) + 2 * i
                                    : reinterpret_cast<const float4*>(enc) + 2 * (i - n_img);
    float4 a = src[0], b = src[1];
    uint4 o;
    o.x = packh2(a.x, a.y); o.y = packh2(a.z, a.w);
    o.z = packh2(b.x, b.y); o.w = packh2(b.z, b.w);
    reinterpret_cast<uint4*>(g_xh)[i] = o;
}

// ---------------- all 4 W fp32 -> fp16, one launch ----------------
__global__ void conv_w4(const float* __restrict__ Wq, const float* __restrict__ Wk,
                        const float* __restrict__ Wv, const float* __restrict__ Wo) {
    const float* src;
    __half* dst;
    switch (blockIdx.y) {
        case 0: src = Wq; dst = g_wqh; break;
        case 1: src = Wk; dst = g_wkh; break;
        case 2: src = Wv; dst = g_wvh; break;
        default: src = Wo; dst = g_woh; break;
    }
    int i = blockIdx.x * 256 + threadIdx.x;
    float4 a = reinterpret_cast<const float4*>(src)[2 * i];
    float4 b = reinterpret_cast<const float4*>(src)[2 * i + 1];
    uint4 o;
    o.x = packh2(a.x, a.y); o.y = packh2(a.z, a.w);
    o.z = packh2(b.x, b.y); o.w = packh2(b.z, b.w);
    reinterpret_cast<uint4*>(dst)[i] = o;
}

// ---------------- shared GEMM mainloop (128x128 tile, BK=64, 3 stages) ----------------
#define GA_PITCH 72                       // halves per A row (64 + 8 pad)
#define GB_PITCH 136                      // halves per B row (128 + 8 pad)
#define GA_BYTES (128 * GA_PITCH * 2)     // 18432
#define GB_BYTES (64 * GB_PITCH * 2)      // 17408
#define GSTAGE   (GA_BYTES + GB_BYTES)    // 35840
#define GEMM_SMEM (3 * GSTAGE)            // 107520

struct GemmCtx {
    int t, lane, warp, wm, wn, grp, kq, row0, col0;
    uint32_t sbase;
};

__device__ __forceinline__ void gemm_mainloop(
    GemmCtx& g, const __half* __restrict__ A, const __half* __restrict__ B,
    float c[4][8][4])
{
    #pragma unroll
    for (int mi = 0; mi < 4; mi++)
        #pragma unroll
        for (int ni = 0; ni < 8; ni++)
            #pragma unroll
            for (int r = 0; r < 4; r++) c[mi][ni][r] = 0.0f;

    const int KT = DIM / 64;   // 48
    auto load_stage = [&](int st, int k0) {
        uint32_t sa = g.sbase + st * GSTAGE;
        uint32_t sb = sa + GA_BYTES;
        #pragma unroll
        for (int i = 0; i < 8; i++) {
            int idx = g.t + i * 128;
            int ar = idx >> 3, ac = idx & 7;
            cpasync16(sa + (ar * GA_PITCH + ac * 8) * 2,
                      A + (size_t)(g.row0 + ar) * DIM + k0 + ac * 8);
            int br = idx >> 4, bc = idx & 15;
            cpasync16(sb + (br * GB_PITCH + bc * 8) * 2,
                      B + (size_t)(k0 + br) * DIM + g.col0 + bc * 8);
        }
    };

    load_stage(0, 0);
    asm volatile("cp.async.commit_group;");
    load_stage(1, 64);
    asm volatile("cp.async.commit_group;");

    const uint32_t aoff = ((g.lane & 15) * GA_PITCH + (g.lane >> 4) * 8) * 2;
    const uint32_t boff = ((g.lane & 15) * GB_PITCH + (g.lane >> 4) * 8) * 2;

    for (int kt = 0; kt < KT; kt++) {
        asm volatile("cp.async.wait_group 1;");
        __syncthreads();

        if (kt + 2 < KT) load_stage((kt + 2) % 3, (kt + 2) * 64);
        asm volatile("cp.async.commit_group;");

        const uint32_t sa = g.sbase + (kt % 3) * GSTAGE;
        const uint32_t sb = sa + GA_BYTES;

        #pragma unroll
        for (int ks = 0; ks < 4; ks++) {
            uint32_t ah[4][4], bh[8][2];
            #pragma unroll
            for (int mi = 0; mi < 4; mi++)
                ldsm4(ah[mi], sa + aoff + ((g.wm + mi * 16) * GA_PITCH + ks * 16) * 2);
            #pragma unroll
            for (int np = 0; np < 4; np++) {
                uint32_t rh[4];
                ldsm4t(rh, sb + boff + (ks * 16 * GB_PITCH + g.wn + np * 16) * 2);
                bh[2 * np][0] = rh[0]; bh[2 * np][1] = rh[1];
                bh[2 * np + 1][0] = rh[2]; bh[2 * np + 1][1] = rh[3];
            }
            #pragma unroll
            for (int mi = 0; mi < 4; mi++)
                #pragma unroll
                for (int ni = 0; ni < 8; ni++)
                    mma_f16(c[mi][ni], ah[mi], bh[ni]);
        }
    }
    __syncthreads();
}

// ---------------- fused QKV GEMM: gridDim.z = 3 selects Q/K/V ----------------
__global__ __launch_bounds__(128, 2) void gemm_qkv(
    const float* __restrict__ bq, const float* __restrict__ bk, const float* __restrict__ bv,
    const float* __restrict__ nqw, const float* __restrict__ nkw,
    const float* __restrict__ rc, const float* __restrict__ rs)
{
    extern __shared__ char smraw[];
    GemmCtx g;
    g.t = threadIdx.x; g.lane = g.t & 31; g.warp = g.t >> 5;
    g.wm = (g.warp & 1) * 64; g.wn = (g.warp >> 1) * 64;
    g.grp = g.lane >> 2; g.kq = g.lane & 3;
    g.row0 = blockIdx.y * 128; g.col0 = blockIdx.x * 128;
    g.sbase = (uint32_t)__cvta_generic_to_shared(smraw);

    const int z = blockIdx.z;
    const __half* B = (z == 0) ? g_wqh : (z == 1) ? g_wkh : g_wvh;
    const float* bias = (z == 0) ? bq : (z == 1) ? bk : bv;

    float c[4][8][4];
    gemm_mainloop(g, g_xh, B, c);

    const bool img = (g.row0 < S_IMG);
    const int wm = g.wm, wn = g.wn, grp = g.grp, kq = g.kq;
    const int row0 = g.row0, col0 = g.col0;

    if (z <= 1) {
        __half* oh = (z == 0) ? g_qh : g_kh;
        const float* nw = (z == 0) ? nqw : nkw;
        const float fold = (z == 0) ? QSCALE : 1.0f;

        float* srow = reinterpret_cast<float*>(smraw);     // [2][128] partial row sums
        const int wnh = wn >> 6;
        float ss0[4], ss1[4];
        #pragma unroll
        for (int mi = 0; mi < 4; mi++) {
            ss0[mi] = 0.0f; ss1[mi] = 0.0f;
            #pragma unroll
            for (int ni = 0; ni < 8; ni++) {
                const int cg = col0 + wn + ni * 8 + 2 * kq;
                float2 bb = *reinterpret_cast<const float2*>(&bias[cg]);
                c[mi][ni][0] += bb.x; c[mi][ni][1] += bb.y;
                c[mi][ni][2] += bb.x; c[mi][ni][3] += bb.y;
                ss0[mi] += c[mi][ni][0] * c[mi][ni][0] + c[mi][ni][1] * c[mi][ni][1];
                ss1[mi] += c[mi][ni][2] * c[mi][ni][2] + c[mi][ni][3] * c[mi][ni][3];
            }
            ss0[mi] += __shfl_xor_sync(0xffffffffu, ss0[mi], 1);
            ss0[mi] += __shfl_xor_sync(0xffffffffu, ss0[mi], 2);
            ss1[mi] += __shfl_xor_sync(0xffffffffu, ss1[mi], 1);
            ss1[mi] += __shfl_xor_sync(0xffffffffu, ss1[mi], 2);
        }
        if (kq == 0) {
            #pragma unroll
            for (int mi = 0; mi < 4; mi++) {
                srow[wnh * 128 + wm + mi * 16 + grp]     = ss0[mi];
                srow[wnh * 128 + wm + mi * 16 + grp + 8] = ss1[mi];
            }
        }
        __syncthreads();
        #pragma unroll
        for (int mi = 0; mi < 4; mi++) {
            const int rl0 = wm + mi * 16 + grp, rl1 = rl0 + 8;
            const int r0 = row0 + rl0, r1 = row0 + rl1;
            const float rr0 = rsqrtf((srow[rl0] + srow[128 + rl0]) * (1.0f / HD) + 1e-6f);
            const float rr1 = rsqrtf((srow[rl1] + srow[128 + rl1]) * (1.0f / HD) + 1e-6f);
            #pragma unroll
            for (int ni = 0; ni < 8; ni++) {
                const int d = wn + ni * 8 + 2 * kq;
                const int cg = col0 + d;
                float2 w2 = *reinterpret_cast<const float2*>(&nw[d]);
                float v0 = c[mi][ni][0] * rr0 * w2.x;
                float v1 = c[mi][ni][1] * rr0 * w2.y;
                float v2 = c[mi][ni][2] * rr1 * w2.x;
                float v3 = c[mi][ni][3] * rr1 * w2.y;
                if (img) {
                    float2 c20 = *reinterpret_cast<const float2*>(&rc[(size_t)r0 * HD + d]);
                    float2 s20 = *reinterpret_cast<const float2*>(&rs[(size_t)r0 * HD + d]);
                    float2 c21 = *reinterpret_cast<const float2*>(&rc[(size_t)r1 * HD + d]);
                    float2 s21 = *reinterpret_cast<const float2*>(&rs[(size_t)r1 * HD + d]);
                    float e0 = v0, o0 = v1, e1 = v2, o1 = v3;
                    v0 = e0 * c20.x - o0 * s20.x;
                    v1 = o0 * c20.y + e0 * s20.y;
                    v2 = e1 * c21.x - o1 * s21.x;
                    v3 = o1 * c21.y + e1 * s21.y;
                }
                v0 *= fold; v1 *= fold; v2 *= fold; v3 *= fold;
                *reinterpret_cast<__half2*>(&oh[(size_t)r0 * DIM + cg]) =
                    __floats2half2_rn(v0, v1);
                *reinterpret_cast<__half2*>(&oh[(size_t)r1 * DIM + cg]) =
                    __floats2half2_rn(v2, v3);
            }
        }
    } else {
        #pragma unroll
        for (int mi = 0; mi < 4; mi++) {
            const int r0 = row0 + wm + mi * 16 + grp, r1 = r0 + 8;
            #pragma unroll
            for (int ni = 0; ni < 8; ni++) {
                const int cg = col0 + wn + ni * 8 + 2 * kq;
                float2 bb = *reinterpret_cast<const float2*>(&bias[cg]);
                *reinterpret_cast<__half2*>(&g_vh[(size_t)r0 * DIM + cg]) =
                    __floats2half2_rn(c[mi][ni][0] + bb.x, c[mi][ni][1] + bb.y);
                *reinterpret_cast<__half2*>(&g_vh[(size_t)r1 * DIM + cg]) =
                    __floats2half2_rn(c[mi][ni][2] + bb.x, c[mi][ni][3] + bb.y);
            }
        }
    }
}

// ---------------- output GEMM: attn(img) @ Wo + bo -> d_out ----------------
__global__ __launch_bounds__(128, 2) void gemm_out(
    const float* __restrict__ bias, float* __restrict__ outF)
{
    extern __shared__ char smraw[];
    GemmCtx g;
    g.t = threadIdx.x; g.lane = g.t & 31; g.warp = g.t >> 5;
    g.wm = (g.warp & 1) * 64; g.wn = (g.warp >> 1) * 64;
    g.grp = g.lane >> 2; g.kq = g.lane & 3;
    g.row0 = blockIdx.y * 128; g.col0 = blockIdx.x * 128;
    g.sbase = (uint32_t)__cvta_generic_to_shared(smraw);

    float c[4][8][4];
    gemm_mainloop(g, g_ah, g_woh, c);

    #pragma unroll
    for (int mi = 0; mi < 4; mi++) {
        const int r0 = g.row0 + g.wm + mi * 16 + g.grp, r1 = r0 + 8;
        #pragma unroll
        for (int ni = 0; ni < 8; ni++) {
            const int cg = g.col0 + g.wn + ni * 8 + 2 * g.kq;
            float2 bb = *reinterpret_cast<const float2*>(&bias[cg]);
            *reinterpret_cast<float2*>(&outF[(size_t)r0 * DIM + cg]) =
                make_float2(c[mi][ni][0] + bb.x, c[mi][ni][1] + bb.y);
            *reinterpret_cast<float2*>(&outF[(size_t)r1 * DIM + cg]) =
                make_float2(c[mi][ni][2] + bb.x, c[mi][ni][3] + bb.y);
        }
    }
}

// ---------------- flash attention: fixed-shift softmax, 128-row Q, 4-stage KV ----------------
// smem (bytes): Q 34816 | K 4 x 17408 | V 4 x 17408  = 174080
#define AO_Q  0
#define AO_K  34816
#define AO_V  104448
#define ATTN_SMEM 174080

__global__ __launch_bounds__(256, 1) void attn_tc(float* __restrict__ out) {
    extern __shared__ __half sh[];
    const int t = threadIdx.x, lane = t & 31, w = t >> 5;
    const int grp = lane >> 2, kq = lane & 3;
    const int h = blockIdx.y, q0 = blockIdx.x * 128, m0 = w * 16;
    const uint32_t sb = (uint32_t)__cvta_generic_to_shared(sh);

    auto load_q = [&]() {
        #pragma unroll
        for (int i = 0; i < 8; i++) {
            int idx = t + i * 256;
            int r = idx >> 4, cch = idx & 15;
            cpasync16(sb + AO_Q + r * 272 + cch * 16,
                      g_qh + (size_t)(q0 + r) * DIM + h * HD + cch * 8);
        }
    };
    auto load_kv = [&](int st, int k0) {
        uint32_t kb = sb + AO_K + st * 17408;
        uint32_t vb = sb + AO_V + st * 17408;
        #pragma unroll
        for (int i = 0; i < 4; i++) {
            int idx = t + i * 256;
            int r = idx >> 4, cch = idx & 15;
            uint32_t off = r * 272 + cch * 16;
            size_t g = (size_t)(k0 + r) * DIM + h * HD + cch * 8;
            cpasync16(kb + off, g_kh + g);
            cpasync16(vb + off, g_vh + g);
        }
    };

    load_q();
    asm volatile("cp.async.commit_group;");
    load_kv(0, 0);
    asm volatile("cp.async.commit_group;");
    load_kv(1, 64);
    asm volatile("cp.async.commit_group;");
    load_kv(2, 128);
    asm volatile("cp.async.commit_group;");

    asm volatile("cp.async.wait_group 3;");   // Q resident
    __syncthreads();

    uint32_t qah[8][4];
    const uint32_t qoff = ((m0 + (lane & 15)) * 272 + (lane >> 4) * 16);
    #pragma unroll
    for (int ks = 0; ks < 8; ks++)
        ldsm4(qah[ks], sb + AO_Q + qoff + ks * 32);

    float O[16][4];
    #pragma unroll
    for (int nt = 0; nt < 16; nt++)
        #pragma unroll
        for (int r = 0; r < 4; r++) O[nt][r] = 0.0f;
    float lrow0 = 0.0f, lrow1 = 0.0f;     // per-lane partial row sums

    const uint32_t koff = ((lane & 15) * 272 + (lane >> 4) * 16);

    for (int kt = 0; kt < 36; kt++) {
        asm volatile("cp.async.wait_group 2;");
        __syncthreads();

        if (kt + 3 < 36) load_kv((kt + 3) & 3, (kt + 3) * 64);
        asm volatile("cp.async.commit_group;");

        const int st = kt & 3;
        const uint32_t kbh = sb + AO_K + st * 17408;
        const uint32_t vbb = sb + AO_V + st * 17408;

        // --- S = Q K^T (single fp16) ---
        float S[8][4];
        #pragma unroll
        for (int n = 0; n < 8; n++)
            #pragma unroll
            for (int r = 0; r < 4; r++) S[n][r] = 0.0f;

        #pragma unroll
        for (int ks = 0; ks < 8; ks++) {
            #pragma unroll
            for (int nb = 0; nb < 4; nb++) {
                uint32_t kh4[4];
                ldsm4(kh4, kbh + koff + nb * 16 * 272 + ks * 32);
                uint32_t bh0[2] = {kh4[0], kh4[2]}, bh1[2] = {kh4[1], kh4[3]};
                mma_f16(S[2 * nb], qah[ks], bh0);
                mma_f16(S[2 * nb + 1], qah[ks], bh1);
            }
        }

        // --- fixed-shift softmax: p = 2^(s - SMAX); no max, no rescale ---
        #pragma unroll
        for (int n = 0; n < 8; n++) {
            S[n][0] = ex2(S[n][0] - SMAX);
            S[n][1] = ex2(S[n][1] - SMAX);
            S[n][2] = ex2(S[n][2] - SMAX);
            S[n][3] = ex2(S[n][3] - SMAX);
            lrow0 += S[n][0] + S[n][1];
            lrow1 += S[n][2] + S[n][3];
        }

        // --- repack P -> A fragments ---
        uint32_t pa[4][4];
        #pragma unroll
        for (int ks2 = 0; ks2 < 4; ks2++) {
            pa[ks2][0] = packh2(S[2 * ks2][0],     S[2 * ks2][1]);
            pa[ks2][1] = packh2(S[2 * ks2][2],     S[2 * ks2][3]);
            pa[ks2][2] = packh2(S[2 * ks2 + 1][0], S[2 * ks2 + 1][1]);
            pa[ks2][3] = packh2(S[2 * ks2 + 1][2], S[2 * ks2 + 1][3]);
        }

        // --- O += P V (V via trans ldmatrix) ---
        #pragma unroll
        for (int ks2 = 0; ks2 < 4; ks2++) {
            #pragma unroll
            for (int db = 0; db < 8; db++) {
                uint32_t v4[4];
                ldsm4t(v4, vbb + koff + (ks2 * 16) * 272 + db * 32);
                uint32_t b0[2] = {v4[0], v4[1]}, b1[2] = {v4[2], v4[3]};
                mma_f16(O[2 * db], pa[ks2], b0);
                mma_f16(O[2 * db + 1], pa[ks2], b1);
            }
        }
    }

    // ---- epilogue: reduce l across the quad once, then normalize ----
    lrow0 += __shfl_xor_sync(0xffffffffu, lrow0, 1);
    lrow0 += __shfl_xor_sync(0xffffffffu, lrow0, 2);
    lrow1 += __shfl_xor_sync(0xffffffffu, lrow1, 1);
    lrow1 += __shfl_xor_sync(0xffffffffu, lrow1, 2);
    const float inv0 = 1.0f / lrow0, inv1 = 1.0f / lrow1;
    const int r = q0 + m0 + grp;
    if (blockIdx.x < 16) {
        #pragma unroll
        for (int nt = 0; nt < 16; nt++) {
            int cc = h * HD + nt * 8 + 2 * kq;
            *reinterpret_cast<__half2*>(&g_ah[(size_t)r * DIM + cc]) =
                __floats2half2_rn(O[nt][0] * inv0, O[nt][1] * inv0);
            *reinterpret_cast<__half2*>(&g_ah[(size_t)(r + 8) * DIM + cc]) =
                __floats2half2_rn(O[nt][2] * inv1, O[nt][3] * inv1);
        }
    } else {
        #pragma unroll
        for (int nt = 0; nt < 16; nt++) {
            int cc = h * HD + nt * 8 + 2 * kq;
            *reinterpret_cast<float2*>(&out[(size_t)r * DIM + cc]) =
                make_float2(O[nt][0] * inv0, O[nt][1] * inv0);
            *reinterpret_cast<float2*>(&out[(size_t)(r + 8) * DIM + cc]) =
                make_float2(O[nt][2] * inv1, O[nt][3] * inv1);
        }
    }
}

// ---------------- launch ----------------
extern "C" void kernel_launch(void* const* d_in, const int* in_sizes, int n_in,
                              void* d_out, int out_size) {
    const float* hid  = (const float*)d_in[0];
    const float* enc  = (const float*)d_in[1];
    const float* rcos = (const float*)d_in[2];
    const float* rsin = (const float*)d_in[3];
    const float* Wq   = (const float*)d_in[4];
    const float* bq   = (const float*)d_in[5];
    const float* Wk   = (const float*)d_in[6];
    const float* bk   = (const float*)d_in[7];
    const float* Wv   = (const float*)d_in[8];
    const float* bv   = (const float*)d_in[9];
    const float* nqw  = (const float*)d_in[10];
    const float* nkw  = (const float*)d_in[11];
    const float* Wo   = (const float*)d_in[12];
    const float* bo   = (const float*)d_in[13];
    float* out = (float*)d_out;

    cudaFuncSetAttribute(gemm_qkv, cudaFuncAttributeMaxDynamicSharedMemorySize, GEMM_SMEM);
    cudaFuncSetAttribute(gemm_out, cudaFuncAttributeMaxDynamicSharedMemorySize, GEMM_SMEM);
    cudaFuncSetAttribute(attn_tc, cudaFuncAttributeMaxDynamicSharedMemorySize, ATTN_SMEM);

    concat_xh<<<SEQ * DIM / 2048, 256>>>(hid, enc);

    dim3 gw(DIM * DIM / 2048, 4);
    conv_w4<<<gw, 256>>>(Wq, Wk, Wv, Wo);

    dim3 gqkv(DIM / 128, SEQ / 128, 3);
    gemm_qkv<<<gqkv, 128, GEMM_SMEM>>>(bq, bk, bv, nqw, nkw, rcos, rsin);

    dim3 ga(SEQ / 128, HEADS);
    attn_tc<<<ga, 256, ATTN_SMEM>>>(out);

    dim3 gout(DIM / 128, S_IMG / 128);
    gemm_out<<<gout, 128, GEMM_SMEM>>>(bo, out);
}